// round 15
// baseline (speedup 1.0000x reference)
#include <cuda_runtime.h>
#include <cuda_fp16.h>
#include <cstdint>
#include <cstddef>

#define Bb 64
#define Ss 512
#define Zz 1024
#define H2 256
#define ZS (Zz*Ss)

// ---------------- static scratch ----------------
__device__ __half g_P[(size_t)Bb*ZS];     // 67MB: exp(lc0 + bout) fp16
__device__ float g_v2[Bb*H2];
__device__ float g_elp2[Bb*Ss];
__device__ float g_u[Bb*Ss];
__device__ float g_lp1[Zz];
__device__ float g_elp1[Zz];
__device__ float g_iR[Bb*Zz];
__device__ float g_cph[2][Bb*Ss];         // per-half column partials
__device__ int   g_bar[Bb];               // cross-CTA barrier counters

// smem layout for k_gemm (dynamic):
//   [0, 66560)        sA: float[64][260]
//   [66560, 100352)   sB: float[4][8][264] (B 4-stage) UNION sO: __half2[64][132]
#define SMEM_B_OFF      66560
#define SMEM_TOTAL_GEMM 100352

// smem layout for k_sinkp2 (dynamic):
//   [0, 65536)            ring: [16 warps][4 rows][1024B]
//   [65536, +2048)        s_ew[512]
//   [67584, +2048)        s_elp2[512]
//   [69632, +2048)        s_elp1h[512]
//   [71680, +2048)        s_red[512]
//   [73728, +32768)       s_part[16][512]
#define SMEM_TOTAL_SINK 106496

// ---------------- zero barrier counters ----------------
__global__ void k_zero() { g_bar[threadIdx.x] = 0; }

// ---------------- prior: lp1 = log_softmax(prior) ----------------
__global__ void k_prior(const float* __restrict__ prior) {
    __shared__ float red[1024];
    int tid = threadIdx.x;
    float x = prior[tid];
    red[tid] = x; __syncthreads();
    for (int o = 512; o > 0; o >>= 1) { if (tid < o) red[tid] = fmaxf(red[tid], red[tid+o]); __syncthreads(); }
    float m = red[0]; __syncthreads();
    float e = __expf(x - m);
    red[tid] = e; __syncthreads();
    for (int o = 512; o > 0; o >>= 1) { if (tid < o) red[tid] += red[tid+o]; __syncthreads(); }
    float lse = m + __logf(red[0]);
    float lp1 = x - lse;
    g_lp1[tid] = lp1;
    g_elp1[tid] = __expf(lp1);
}

// ---------------- MLP ----------------
__global__ void k_mlp(const float* __restrict__ sl, const float* __restrict__ W1,
                      const float* __restrict__ b1, const float* __restrict__ W2,
                      const float* __restrict__ b2) {
    __shared__ float sv[Ss];
    __shared__ float v1s[Ss];
    __shared__ float red[Ss];
    int b = blockIdx.x, tid = threadIdx.x;
    float x = sl[b*Ss + tid];
    red[tid] = x; __syncthreads();
    for (int o = 256; o > 0; o >>= 1) { if (tid < o) red[tid] = fmaxf(red[tid], red[tid+o]); __syncthreads(); }
    float m = red[0]; __syncthreads();
    float e = __expf(x - m);
    red[tid] = e; __syncthreads();
    for (int o = 256; o > 0; o >>= 1) { if (tid < o) red[tid] += red[tid+o]; __syncthreads(); }
    float inv = 1.0f / red[0];
    float v = e * inv;
    sv[tid] = v;
    g_elp2[b*Ss + tid] = v;
    __syncthreads();
    float acc = b1[tid];
    #pragma unroll 4
    for (int s = 0; s < Ss; s++) acc = fmaf(sv[s], W1[s*512 + tid], acc);
    v1s[tid] = 1.0f / (1.0f + __expf(-acc));
    __syncthreads();
    if (tid < H2) {
        float a2 = b2[tid];
        #pragma unroll 4
        for (int h = 0; h < 512; h++) a2 = fmaf(v1s[h], W2[h*H2 + tid], a2);
        g_v2[b*H2 + tid] = 1.0f / (1.0f + __expf(-a2));
    }
}

// ---------------- GEMM (proven 4-stage, 149.5us) ----------------
__device__ __forceinline__ void mma8(float* c, uint32_t a0, uint32_t a1, uint32_t a2, uint32_t a3,
                                     uint32_t b0, uint32_t b1) {
    asm volatile(
        "mma.sync.aligned.m16n8k8.row.col.f32.tf32.tf32.f32 "
        "{%0,%1,%2,%3},{%4,%5,%6,%7},{%8,%9},{%0,%1,%2,%3};"
        : "+f"(c[0]), "+f"(c[1]), "+f"(c[2]), "+f"(c[3])
        : "r"(a0), "r"(a1), "r"(a2), "r"(a3), "r"(b0), "r"(b1));
}

__device__ __forceinline__ void cp16(uint32_t saddr, const void* gptr) {
    asm volatile("cp.async.cg.shared.global [%0], [%1], 16;" :: "r"(saddr), "l"(gptr));
}

__global__ void __launch_bounds__(256, 2) k_gemm(const float* __restrict__ Wout,
                                                 const float* __restrict__ bout) {
    extern __shared__ __align__(16) unsigned char smem_raw[];
    float* sA = (float*)smem_raw;                                   // [64][260]
    float (*sB)[8][264] = (float (*)[8][264])(smem_raw + SMEM_B_OFF);
    __half2 (*sO)[132] = (__half2 (*)[132])(smem_raw + SMEM_B_OFF);
    uint32_t sbbase = (uint32_t)__cvta_generic_to_shared(smem_raw + SMEM_B_OFF);

    int tid = threadIdx.x, wid = tid >> 5, lane = tid & 31;
    int gid = lane >> 2, tig = lane & 3;
    int n0 = blockIdx.x * 256;

    int kr = tid >> 5;
    int c0 = (tid & 31) * 8;

    #pragma unroll
    for (int ii = 0; ii < 64; ii++) {
        int idx = ii*256 + tid;
        int m = idx >> 8, k = idx & 255;
        sA[m*260 + k] = g_v2[idx];
    }

    float c[4][4][4];
    #pragma unroll
    for (int mt = 0; mt < 4; mt++)
        #pragma unroll
        for (int nt = 0; nt < 4; nt++)
            { c[mt][nt][0]=0.f; c[mt][nt][1]=0.f; c[mt][nt][2]=0.f; c[mt][nt][3]=0.f; }

    #pragma unroll
    for (int s = 0; s < 3; s++) {
        const float* src = Wout + (size_t)(s*8 + kr)*ZS + n0 + c0;
        uint32_t dst = sbbase + (uint32_t)((s*8 + kr)*264 + c0) * 4u;
        cp16(dst, src);
        cp16(dst + 16, src + 4);
        asm volatile("cp.async.commit_group;");
    }
    __syncthreads();

    for (int j = 0; j < 32; j++) {
        if (j < 30)       asm volatile("cp.async.wait_group 2;");
        else if (j == 30) asm volatile("cp.async.wait_group 1;");
        else              asm volatile("cp.async.wait_group 0;");
        __syncthreads();
        if (j + 3 < 32) {
            int s = (j + 3) & 3;
            const float* src = Wout + (size_t)((j+3)*8 + kr)*ZS + n0 + c0;
            uint32_t dst = sbbase + (uint32_t)((s*8 + kr)*264 + c0) * 4u;
            cp16(dst, src);
            cp16(dst + 16, src + 4);
            asm volatile("cp.async.commit_group;");
        }
        int buf = j & 3;
        int k0 = j * 8;
        uint32_t a0[4], a1[4], a2[4], a3[4];
        #pragma unroll
        for (int mt = 0; mt < 4; mt++) {
            a0[mt] = __float_as_uint(sA[(mt*16+gid  )*260 + k0 + tig    ]);
            a1[mt] = __float_as_uint(sA[(mt*16+gid+8)*260 + k0 + tig    ]);
            a2[mt] = __float_as_uint(sA[(mt*16+gid  )*260 + k0 + tig + 4]);
            a3[mt] = __float_as_uint(sA[(mt*16+gid+8)*260 + k0 + tig + 4]);
        }
        #pragma unroll
        for (int nt = 0; nt < 4; nt++) {
            int colb = wid*32 + nt*8 + gid;
            uint32_t b0 = __float_as_uint(sB[buf][tig  ][colb]);
            uint32_t b1 = __float_as_uint(sB[buf][tig+4][colb]);
            #pragma unroll
            for (int mt = 0; mt < 4; mt++)
                mma8(c[mt][nt], a0[mt], a1[mt], a2[mt], a3[mt], b0, b1);
        }
    }
    __syncthreads();

    #pragma unroll
    for (int nt = 0; nt < 4; nt++) {
        int colp = wid*16 + nt*4 + tig;
        float bo0 = bout[n0 + colp*2];
        float bo1 = bout[n0 + colp*2 + 1];
        #pragma unroll
        for (int mt = 0; mt < 4; mt++) {
            int r0 = mt*16 + gid;
            sO[r0  ][colp] = __floats2half2_rn(__expf(c[mt][nt][0]+bo0), __expf(c[mt][nt][1]+bo1));
            sO[r0+8][colp] = __floats2half2_rn(__expf(c[mt][nt][2]+bo0), __expf(c[mt][nt][3]+bo1));
        }
    }
    __syncthreads();
    int r = tid >> 2;
    #pragma unroll
    for (int pass = 0; pass < 8; pass++) {
        int u = (tid & 3) + 4*pass;
        uint4 v = *(uint4*)&sO[r][u*4];
        ((uint4*)(g_P + (size_t)r*ZS + n0))[u] = v;
    }
}

// ---------------- helpers ----------------
__device__ __forceinline__ void unpack8(uint4 q, float* p) {
    float2 f;
    f = __half22float2(*(__half2*)&q.x); p[0]=f.x; p[1]=f.y;
    f = __half22float2(*(__half2*)&q.y); p[2]=f.x; p[3]=f.y;
    f = __half22float2(*(__half2*)&q.z); p[4]=f.x; p[5]=f.y;
    f = __half22float2(*(__half2*)&q.w); p[6]=f.x; p[7]=f.y;
}

// ---------------- persistent Sinkhorn, 2 CTAs/batch, cp.async row ring ----------------
// grid = 128: blockIdx.x = batch*2 + half. 512 thr, 16 warps x 32 rows.
// Each warp streams its rows through a private 4-row (4KB) smem ring via cp.async:
// 64KB in flight per SM -> L2-bandwidth-bound instead of latency-bound.
__global__ void __launch_bounds__(512, 1) k_sinkp2() {
    extern __shared__ __align__(16) unsigned char dyn[];
    unsigned char* ring = dyn;                              // [16][4][1024]
    float* s_ew    = (float*)(dyn + 65536);
    float* s_elp2  = (float*)(dyn + 67584);
    float* s_elp1h = (float*)(dyn + 69632);
    float* s_red   = (float*)(dyn + 71680);
    float (*s_part)[512] = (float (*)[512])(dyn + 73728);

    int b = blockIdx.x >> 1, half = blockIdx.x & 1;
    int tid = threadIdx.x;
    int w = tid >> 5, lane = tid & 31;

    s_elp2[tid]  = g_elp2[b*Ss + tid];
    s_elp1h[tid] = g_elp1[half*512 + tid];
    __syncthreads();

    const char* PbC = (const char*)(g_P + (size_t)b*ZS);   // row stride 1024B
    uint32_t ringbase = (uint32_t)__cvta_generic_to_shared(ring) + (uint32_t)w*4096;
    const uint4* ringw = (const uint4*)(ring + w*4096);
    int rowbase = half*512 + w*32;
    float my_part = 0.f;

    for (int it = 0; it <= 10; it++) {
        float ew;
        if (it == 0) ew = 1.0f;
        else {
            float other = g_cph[1 - half][b*Ss + tid];
            ew = s_elp2[tid] / (my_part + other);
        }
        s_ew[tid] = ew;
        __syncthreads();

        float ewr[16], colacc[16];
        #pragma unroll
        for (int i = 0; i < 8; i++) {
            ewr[i]   = s_ew[8*lane + i];
            ewr[8+i] = s_ew[256 + 8*lane + i];
            colacc[i] = 0.f; colacc[8+i] = 0.f;
        }

        // prologue: prefetch rows 0..3 into ring
        #pragma unroll
        for (int d = 0; d < 4; d++) {
            const char* src = PbC + (size_t)(rowbase + d)*1024 + lane*32;
            uint32_t dst = ringbase + d*1024 + lane*32;
            cp16(dst, src);
            cp16(dst + 16, src + 16);
            asm volatile("cp.async.commit_group;");
        }

        #pragma unroll
        for (int r = 0; r < 32; r++) {
            // tail-exact: issued = 4+min(r,28) groups; need row r (r+1 groups) done.
            if (r < 29)       asm volatile("cp.async.wait_group 3;");
            else if (r == 29) asm volatile("cp.async.wait_group 2;");
            else if (r == 30) asm volatile("cp.async.wait_group 1;");
            else              asm volatile("cp.async.wait_group 0;");
            __syncwarp();
            const uint4* slot = ringw + (size_t)(r & 3)*64;
            uint4 q0 = slot[lane];
            uint4 q1 = slot[lane + 32];
            float p[16];
            unpack8(q0, p); unpack8(q1, p+8);   // consumes q -> LDS complete
            __syncwarp();                        // all lanes done reading slot
            if (r + 4 < 32) {
                int d = r + 4;
                const char* src = PbC + (size_t)(rowbase + d)*1024 + lane*32;
                uint32_t dst = ringbase + (d & 3)*1024 + lane*32;
                cp16(dst, src);
                cp16(dst + 16, src + 16);
                asm volatile("cp.async.commit_group;");
            }
            float rs = 0.f;
            #pragma unroll
            for (int i = 0; i < 16; i++) rs = fmaf(p[i], ewr[i], rs);
            #pragma unroll
            for (int o = 16; o > 0; o >>= 1) rs += __shfl_xor_sync(0xFFFFFFFFu, rs, o);
            float irs = 1.0f / rs;
            if (it == 10 && lane == 0) g_iR[b*Zz + rowbase + r] = irs;
            float ea = s_elp1h[w*32 + r] * irs;
            #pragma unroll
            for (int i = 0; i < 16; i++) colacc[i] = fmaf(p[i], ea, colacc[i]);
        }
        *(float4*)&s_part[w][8*lane]           = make_float4(colacc[0],  colacc[1],  colacc[2],  colacc[3]);
        *(float4*)&s_part[w][8*lane + 4]       = make_float4(colacc[4],  colacc[5],  colacc[6],  colacc[7]);
        *(float4*)&s_part[w][256 + 8*lane]     = make_float4(colacc[8],  colacc[9],  colacc[10], colacc[11]);
        *(float4*)&s_part[w][256 + 8*lane + 4] = make_float4(colacc[12], colacc[13], colacc[14], colacc[15]);
        __syncthreads();
        float sum = 0.f;
        #pragma unroll
        for (int ww = 0; ww < 16; ww++) sum += s_part[ww][tid];
        my_part = sum;
        g_cph[half][b*Ss + tid] = sum;
        __syncthreads();
        if (tid == 0) {
            int target = 2 * (it + 1);
            asm volatile("red.release.gpu.global.add.s32 [%0], 1;"
                         :: "l"(&g_bar[b]) : "memory");
            int v;
            do {
                asm volatile("ld.acquire.gpu.global.s32 %0, [%1];"
                             : "=r"(v) : "l"(&g_bar[b]) : "memory");
            } while (v < target);
        }
        __syncthreads();
    }

    float other = g_cph[1 - half][b*Ss + tid];
    float colsum = my_part + other;
    float A = s_elp2[tid] / (s_ew[tid] * colsum);
    s_red[tid] = A; __syncthreads();
    for (int o = 256; o > 0; o >>= 1) { if (tid < o) s_red[tid] = fmaxf(s_red[tid], s_red[tid+o]); __syncthreads(); }
    float mx = s_red[0];
    if (half == 0) g_u[b*Ss + tid] = s_ew[tid] * A / mx;
}

// ---------------- fused keep+final ----------------
__global__ void __launch_bounds__(256, 4) k_kf(float* __restrict__ out) {
    int b = blockIdx.y, chunk = blockIdx.x, tid = threadIdx.x;
    __shared__ float s_u[Ss];
    __shared__ float s_e2[Ss];
    #pragma unroll
    for (int h = 0; h < 2; h++) {
        int s = tid + 256*h;
        s_u[s]  = g_u[b*Ss + s];
        s_e2[s] = g_elp2[b*Ss + s];
    }
    __syncthreads();
    int wid = tid >> 5, lane = tid & 31;
    float ur[16], er[16];
    #pragma unroll
    for (int i = 0; i < 8; i++) {
        ur[i]   = s_u[8*lane + i];    ur[8+i] = s_u[256 + 8*lane + i];
        er[i]   = s_e2[8*lane + i];   er[8+i] = s_e2[256 + 8*lane + i];
    }
    const uint4* Pb = (const uint4*)(g_P + (size_t)b*ZS);
    float* Ob = out + (size_t)b*ZS;
    #pragma unroll
    for (int r = 0; r < 8; r++) {
        int z = chunk*64 + wid*8 + r;
        uint4 q0 = Pb[(size_t)z*64 + lane];
        uint4 q1 = Pb[(size_t)z*64 + 32 + lane];
        float p[16];
        unpack8(q0, p); unpack8(q1, p+8);
        float ks = 0.f;
        #pragma unroll
        for (int i = 0; i < 16; i++) ks = fmaf(p[i], ur[i], ks);
        #pragma unroll
        for (int o = 16; o > 0; o >>= 1) ks += __shfl_xor_sync(0xFFFFFFFFu, ks, o);
        float iR = g_iR[b*Zz + z];
        float K = iR * ks;
        float eres = fmaxf(0.f, 1.f - K);
        float l1 = g_lp1[z];
        float v[16];
        #pragma unroll
        for (int i = 0; i < 16; i++)
            v[i] = l1 + __logf(fmaf(p[i], ur[i]*iR, eres*er[i]));
        float* o0 = Ob + (size_t)z*512 + 8*lane;
        float* o1 = o0 + 256;
        *(float4*)(o0    ) = make_float4(v[0], v[1], v[2], v[3]);
        *(float4*)(o0 + 4) = make_float4(v[4], v[5], v[6], v[7]);
        *(float4*)(o1    ) = make_float4(v[8], v[9], v[10], v[11]);
        *(float4*)(o1 + 4) = make_float4(v[12], v[13], v[14], v[15]);
    }
}

// ---------------- launch ----------------
extern "C" void kernel_launch(void* const* d_in, const int* in_sizes, int n_in,
                              void* d_out, int out_size) {
    const float* s_logits = (const float*)d_in[0];
    const float* W1   = (const float*)d_in[1];
    const float* b1   = (const float*)d_in[2];
    const float* W2   = (const float*)d_in[3];
    const float* b2   = (const float*)d_in[4];
    const float* Wout = (const float*)d_in[5];
    const float* bout = (const float*)d_in[6];
    const float* prior= (const float*)d_in[7];
    float* out = (float*)d_out;
    (void)in_sizes; (void)n_in; (void)out_size;

    cudaFuncSetAttribute(k_gemm, cudaFuncAttributeMaxDynamicSharedMemorySize, SMEM_TOTAL_GEMM);
    cudaFuncSetAttribute(k_sinkp2, cudaFuncAttributeMaxDynamicSharedMemorySize, SMEM_TOTAL_SINK);

    k_zero<<<1, Bb>>>();
    k_prior<<<1, 1024>>>(prior);
    k_mlp<<<Bb, 512>>>(s_logits, W1, b1, W2, b2);
    k_gemm<<<2048, 256, SMEM_TOTAL_GEMM>>>(Wout, bout);
    k_sinkp2<<<2*Bb, 512, SMEM_TOTAL_SINK>>>();
    k_kf<<<dim3(16, Bb), 256>>>(out);
}

// round 16
// speedup vs baseline: 1.0305x; 1.0305x over previous
#include <cuda_runtime.h>
#include <cuda_fp16.h>
#include <cstdint>
#include <cstddef>

#define Bb 64
#define Ss 512
#define Zz 1024
#define H2 256
#define ZS (Zz*Ss)

// ---------------- static scratch ----------------
__device__ __half g_P[(size_t)Bb*ZS];     // 67MB: exp(lc0 + bout) fp16
__device__ float g_v2[Bb*H2];
__device__ float g_elp2[Bb*Ss];
__device__ float g_lp1[Zz];
__device__ float g_elp1[Zz];
__device__ float g_cph[2][Bb*Ss];         // per-half column partials
__device__ int   g_bar[Bb];               // cross-CTA barrier counters

// smem layout for k_gemm (dynamic):
//   [0, 66560)        sA: float[64][260]
//   [66560, 100352)   sB: float[4][8][264] (B 4-stage) UNION sO: __half2[64][132]
#define SMEM_B_OFF      66560
#define SMEM_TOTAL_GEMM 100352

// smem layout for k_sinkp2 (dynamic):
//   [0, 131072)       ring: [16 warps][8 rows][1024B]
//   +131072 s_ew[512] (later reused as s_u)
//   +133120 s_elp2[512]
//   +135168 s_elp1h[512]
//   +137216 s_red[512]
//   +139264 s_irs[512]
//   +141312 s_lp1h[512]
//   +143360 s_part[16][512]   (32KB) -> end 176128
#define SMEM_TOTAL_SINK 176128

// ---------------- prior: lp1 = log_softmax(prior); also zero barrier ctrs ----------------
__global__ void k_prior(const float* __restrict__ prior) {
    __shared__ float red[1024];
    int tid = threadIdx.x;
    if (tid < Bb) g_bar[tid] = 0;
    float x = prior[tid];
    red[tid] = x; __syncthreads();
    for (int o = 512; o > 0; o >>= 1) { if (tid < o) red[tid] = fmaxf(red[tid], red[tid+o]); __syncthreads(); }
    float m = red[0]; __syncthreads();
    float e = __expf(x - m);
    red[tid] = e; __syncthreads();
    for (int o = 512; o > 0; o >>= 1) { if (tid < o) red[tid] += red[tid+o]; __syncthreads(); }
    float lse = m + __logf(red[0]);
    float lp1 = x - lse;
    g_lp1[tid] = lp1;
    g_elp1[tid] = __expf(lp1);
}

// ---------------- MLP ----------------
__global__ void k_mlp(const float* __restrict__ sl, const float* __restrict__ W1,
                      const float* __restrict__ b1, const float* __restrict__ W2,
                      const float* __restrict__ b2) {
    __shared__ float sv[Ss];
    __shared__ float v1s[Ss];
    __shared__ float red[Ss];
    int b = blockIdx.x, tid = threadIdx.x;
    float x = sl[b*Ss + tid];
    red[tid] = x; __syncthreads();
    for (int o = 256; o > 0; o >>= 1) { if (tid < o) red[tid] = fmaxf(red[tid], red[tid+o]); __syncthreads(); }
    float m = red[0]; __syncthreads();
    float e = __expf(x - m);
    red[tid] = e; __syncthreads();
    for (int o = 256; o > 0; o >>= 1) { if (tid < o) red[tid] += red[tid+o]; __syncthreads(); }
    float inv = 1.0f / red[0];
    float v = e * inv;
    sv[tid] = v;
    g_elp2[b*Ss + tid] = v;
    __syncthreads();
    float acc = b1[tid];
    #pragma unroll 4
    for (int s = 0; s < Ss; s++) acc = fmaf(sv[s], W1[s*512 + tid], acc);
    v1s[tid] = 1.0f / (1.0f + __expf(-acc));
    __syncthreads();
    if (tid < H2) {
        float a2 = b2[tid];
        #pragma unroll 4
        for (int h = 0; h < 512; h++) a2 = fmaf(v1s[h], W2[h*H2 + tid], a2);
        g_v2[b*H2 + tid] = 1.0f / (1.0f + __expf(-a2));
    }
}

// ---------------- GEMM (proven 4-stage, 149.5us) ----------------
__device__ __forceinline__ void mma8(float* c, uint32_t a0, uint32_t a1, uint32_t a2, uint32_t a3,
                                     uint32_t b0, uint32_t b1) {
    asm volatile(
        "mma.sync.aligned.m16n8k8.row.col.f32.tf32.tf32.f32 "
        "{%0,%1,%2,%3},{%4,%5,%6,%7},{%8,%9},{%0,%1,%2,%3};"
        : "+f"(c[0]), "+f"(c[1]), "+f"(c[2]), "+f"(c[3])
        : "r"(a0), "r"(a1), "r"(a2), "r"(a3), "r"(b0), "r"(b1));
}

__device__ __forceinline__ void cp16(uint32_t saddr, const void* gptr) {
    asm volatile("cp.async.cg.shared.global [%0], [%1], 16;" :: "r"(saddr), "l"(gptr));
}

__global__ void __launch_bounds__(256, 2) k_gemm(const float* __restrict__ Wout,
                                                 const float* __restrict__ bout) {
    extern __shared__ __align__(16) unsigned char smem_raw[];
    float* sA = (float*)smem_raw;                                   // [64][260]
    float (*sB)[8][264] = (float (*)[8][264])(smem_raw + SMEM_B_OFF);
    __half2 (*sO)[132] = (__half2 (*)[132])(smem_raw + SMEM_B_OFF);
    uint32_t sbbase = (uint32_t)__cvta_generic_to_shared(smem_raw + SMEM_B_OFF);

    int tid = threadIdx.x, wid = tid >> 5, lane = tid & 31;
    int gid = lane >> 2, tig = lane & 3;
    int n0 = blockIdx.x * 256;

    int kr = tid >> 5;
    int c0 = (tid & 31) * 8;

    #pragma unroll
    for (int ii = 0; ii < 64; ii++) {
        int idx = ii*256 + tid;
        int m = idx >> 8, k = idx & 255;
        sA[m*260 + k] = g_v2[idx];
    }

    float c[4][4][4];
    #pragma unroll
    for (int mt = 0; mt < 4; mt++)
        #pragma unroll
        for (int nt = 0; nt < 4; nt++)
            { c[mt][nt][0]=0.f; c[mt][nt][1]=0.f; c[mt][nt][2]=0.f; c[mt][nt][3]=0.f; }

    #pragma unroll
    for (int s = 0; s < 3; s++) {
        const float* src = Wout + (size_t)(s*8 + kr)*ZS + n0 + c0;
        uint32_t dst = sbbase + (uint32_t)((s*8 + kr)*264 + c0) * 4u;
        cp16(dst, src);
        cp16(dst + 16, src + 4);
        asm volatile("cp.async.commit_group;");
    }
    __syncthreads();

    for (int j = 0; j < 32; j++) {
        if (j < 30)       asm volatile("cp.async.wait_group 2;");
        else if (j == 30) asm volatile("cp.async.wait_group 1;");
        else              asm volatile("cp.async.wait_group 0;");
        __syncthreads();
        if (j + 3 < 32) {
            int s = (j + 3) & 3;
            const float* src = Wout + (size_t)((j+3)*8 + kr)*ZS + n0 + c0;
            uint32_t dst = sbbase + (uint32_t)((s*8 + kr)*264 + c0) * 4u;
            cp16(dst, src);
            cp16(dst + 16, src + 4);
            asm volatile("cp.async.commit_group;");
        }
        int buf = j & 3;
        int k0 = j * 8;
        uint32_t a0[4], a1[4], a2[4], a3[4];
        #pragma unroll
        for (int mt = 0; mt < 4; mt++) {
            a0[mt] = __float_as_uint(sA[(mt*16+gid  )*260 + k0 + tig    ]);
            a1[mt] = __float_as_uint(sA[(mt*16+gid+8)*260 + k0 + tig    ]);
            a2[mt] = __float_as_uint(sA[(mt*16+gid  )*260 + k0 + tig + 4]);
            a3[mt] = __float_as_uint(sA[(mt*16+gid+8)*260 + k0 + tig + 4]);
        }
        #pragma unroll
        for (int nt = 0; nt < 4; nt++) {
            int colb = wid*32 + nt*8 + gid;
            uint32_t b0 = __float_as_uint(sB[buf][tig  ][colb]);
            uint32_t b1 = __float_as_uint(sB[buf][tig+4][colb]);
            #pragma unroll
            for (int mt = 0; mt < 4; mt++)
                mma8(c[mt][nt], a0[mt], a1[mt], a2[mt], a3[mt], b0, b1);
        }
    }
    __syncthreads();

    #pragma unroll
    for (int nt = 0; nt < 4; nt++) {
        int colp = wid*16 + nt*4 + tig;
        float bo0 = bout[n0 + colp*2];
        float bo1 = bout[n0 + colp*2 + 1];
        #pragma unroll
        for (int mt = 0; mt < 4; mt++) {
            int r0 = mt*16 + gid;
            sO[r0  ][colp] = __floats2half2_rn(__expf(c[mt][nt][0]+bo0), __expf(c[mt][nt][1]+bo1));
            sO[r0+8][colp] = __floats2half2_rn(__expf(c[mt][nt][2]+bo0), __expf(c[mt][nt][3]+bo1));
        }
    }
    __syncthreads();
    int r = tid >> 2;
    #pragma unroll
    for (int pass = 0; pass < 8; pass++) {
        int u = (tid & 3) + 4*pass;
        uint4 v = *(uint4*)&sO[r][u*4];
        ((uint4*)(g_P + (size_t)r*ZS + n0))[u] = v;
    }
}

// ---------------- helpers ----------------
__device__ __forceinline__ void unpack8(uint4 q, float* p) {
    float2 f;
    f = __half22float2(*(__half2*)&q.x); p[0]=f.x; p[1]=f.y;
    f = __half22float2(*(__half2*)&q.y); p[2]=f.x; p[3]=f.y;
    f = __half22float2(*(__half2*)&q.z); p[4]=f.x; p[5]=f.y;
    f = __half22float2(*(__half2*)&q.w); p[6]=f.x; p[7]=f.y;
}

// ---------------- persistent Sinkhorn + accept + keep/final, 2 CTAs/batch ----------------
// grid = 128: blockIdx.x = batch*2 + half. 512 thr, 16 warps x 32 rows.
// 8-row warp-private cp.async ring, 2-row commit groups, 2-row interleaved math
// (doubles independent FMA/SHFL chains per warp). After it10: accept computed by
// BOTH CTAs (colsum identical), then keep+final as a 12th ring pass per warp.
__global__ void __launch_bounds__(512, 1) k_sinkp2(float* __restrict__ out) {
    extern __shared__ __align__(16) unsigned char dyn[];
    unsigned char* ring = dyn;                               // [16][8][1024]
    float* s_ew    = (float*)(dyn + 131072);                 // later: s_u
    float* s_elp2  = (float*)(dyn + 133120);
    float* s_elp1h = (float*)(dyn + 135168);
    float* s_red   = (float*)(dyn + 137216);
    float* s_irs   = (float*)(dyn + 139264);
    float* s_lp1h  = (float*)(dyn + 141312);
    float (*s_part)[512] = (float (*)[512])(dyn + 143360);

    int b = blockIdx.x >> 1, half = blockIdx.x & 1;
    int tid = threadIdx.x;
    int w = tid >> 5, lane = tid & 31;

    s_elp2[tid]  = g_elp2[b*Ss + tid];
    s_elp1h[tid] = g_elp1[half*512 + tid];
    s_lp1h[tid]  = g_lp1[half*512 + tid];
    __syncthreads();

    const char* PbC = (const char*)(g_P + (size_t)b*ZS);    // row stride 1024B
    uint32_t ringbase = (uint32_t)__cvta_generic_to_shared(ring) + (uint32_t)w*8192;
    const uint4* ringw = (const uint4*)(ring + w*8192);
    int rowbase = half*512 + w*32;
    float my_part = 0.f;

    for (int it = 0; it <= 10; it++) {
        float ew;
        if (it == 0) ew = 1.0f;
        else {
            float other = g_cph[1 - half][b*Ss + tid];
            ew = s_elp2[tid] / (my_part + other);
        }
        s_ew[tid] = ew;
        __syncthreads();

        float ewr[16], colacc[16];
        #pragma unroll
        for (int i = 0; i < 8; i++) {
            ewr[i]   = s_ew[8*lane + i];
            ewr[8+i] = s_ew[256 + 8*lane + i];
            colacc[i] = 0.f; colacc[8+i] = 0.f;
        }

        // prologue: 3 groups (rows 0..5)
        #pragma unroll
        for (int gg = 0; gg < 3; gg++) {
            #pragma unroll
            for (int rr = 0; rr < 2; rr++) {
                int d = 2*gg + rr;
                const char* src = PbC + (size_t)(rowbase + d)*1024 + lane*32;
                uint32_t dst = ringbase + d*1024 + lane*32;
                cp16(dst, src);
                cp16(dst + 16, src + 16);
            }
            asm volatile("cp.async.commit_group;");
        }

        #pragma unroll 4
        for (int g = 0; g < 16; g++) {
            // tail-exact: issued = 3+min(g,13); need groups 0..g -> pending 2/1/0
            if (g < 14)       asm volatile("cp.async.wait_group 2;");
            else if (g == 14) asm volatile("cp.async.wait_group 1;");
            else              asm volatile("cp.async.wait_group 0;");
            __syncwarp();
            int r0 = 2*g, r1 = 2*g + 1;
            const uint4* sl0 = ringw + (size_t)(r0 & 7)*64;
            const uint4* sl1 = ringw + (size_t)(r1 & 7)*64;
            uint4 qa = sl0[lane], qb = sl0[lane + 32];
            uint4 qc = sl1[lane], qd = sl1[lane + 32];
            float p0[16], p1[16];
            unpack8(qa, p0); unpack8(qb, p0+8);
            unpack8(qc, p1); unpack8(qd, p1+8);
            __syncwarp();
            if (g + 3 < 16) {
                #pragma unroll
                for (int rr = 0; rr < 2; rr++) {
                    int d = 2*(g+3) + rr;
                    const char* src = PbC + (size_t)(rowbase + d)*1024 + lane*32;
                    uint32_t dst = ringbase + (d & 7)*1024 + lane*32;
                    cp16(dst, src);
                    cp16(dst + 16, src + 16);
                }
                asm volatile("cp.async.commit_group;");
            }
            // 4 independent FMA chains (2 rows x 2 halves)
            float rs0a = 0.f, rs0b = 0.f, rs1a = 0.f, rs1b = 0.f;
            #pragma unroll
            for (int i = 0; i < 8; i++) {
                rs0a = fmaf(p0[i],   ewr[i],   rs0a);
                rs0b = fmaf(p0[8+i], ewr[8+i], rs0b);
                rs1a = fmaf(p1[i],   ewr[i],   rs1a);
                rs1b = fmaf(p1[8+i], ewr[8+i], rs1b);
            }
            float rs0 = rs0a + rs0b, rs1 = rs1a + rs1b;
            #pragma unroll
            for (int o = 16; o > 0; o >>= 1) {
                rs0 += __shfl_xor_sync(0xFFFFFFFFu, rs0, o);
                rs1 += __shfl_xor_sync(0xFFFFFFFFu, rs1, o);
            }
            float irs0 = 1.0f / rs0, irs1 = 1.0f / rs1;
            if (it == 10 && lane == 0) {
                s_irs[w*32 + r0] = irs0;
                s_irs[w*32 + r1] = irs1;
            }
            float ea0 = s_elp1h[w*32 + r0] * irs0;
            float ea1 = s_elp1h[w*32 + r1] * irs1;
            #pragma unroll
            for (int i = 0; i < 16; i++) {
                colacc[i] = fmaf(p0[i], ea0, colacc[i]);
                colacc[i] = fmaf(p1[i], ea1, colacc[i]);
            }
        }
        *(float4*)&s_part[w][8*lane]           = make_float4(colacc[0],  colacc[1],  colacc[2],  colacc[3]);
        *(float4*)&s_part[w][8*lane + 4]       = make_float4(colacc[4],  colacc[5],  colacc[6],  colacc[7]);
        *(float4*)&s_part[w][256 + 8*lane]     = make_float4(colacc[8],  colacc[9],  colacc[10], colacc[11]);
        *(float4*)&s_part[w][256 + 8*lane + 4] = make_float4(colacc[12], colacc[13], colacc[14], colacc[15]);
        __syncthreads();
        float sum = 0.f;
        #pragma unroll
        for (int ww = 0; ww < 16; ww++) sum += s_part[ww][tid];
        my_part = sum;
        g_cph[half][b*Ss + tid] = sum;
        __syncthreads();
        if (tid == 0) {
            int target = 2 * (it + 1);
            asm volatile("red.release.gpu.global.add.s32 [%0], 1;"
                         :: "l"(&g_bar[b]) : "memory");
            int v;
            do {
                asm volatile("ld.acquire.gpu.global.s32 %0, [%1];"
                             : "=r"(v) : "l"(&g_bar[b]) : "memory");
            } while (v < target);
        }
        __syncthreads();
    }

    // ---- accept (both CTAs; colsum identical in both halves) ----
    float other = g_cph[1 - half][b*Ss + tid];
    float colsum = my_part + other;
    float A = s_elp2[tid] / (s_ew[tid] * colsum);
    s_red[tid] = A; __syncthreads();
    for (int o = 256; o > 0; o >>= 1) { if (tid < o) s_red[tid] = fmaxf(s_red[tid], s_red[tid+o]); __syncthreads(); }
    float mx = s_red[0];
    float u = s_ew[tid] * A / mx;
    __syncthreads();
    s_ew[tid] = u;           // s_ew now holds u
    __syncthreads();

    // ---- keep + final: 12th ring pass over this warp's 32 rows ----
    float ur[16], er[16];
    #pragma unroll
    for (int i = 0; i < 8; i++) {
        ur[i]   = s_ew[8*lane + i];    ur[8+i] = s_ew[256 + 8*lane + i];
        er[i]   = s_elp2[8*lane + i];  er[8+i] = s_elp2[256 + 8*lane + i];
    }
    float* Ob = out + (size_t)b*ZS;

    #pragma unroll
    for (int gg = 0; gg < 3; gg++) {
        #pragma unroll
        for (int rr = 0; rr < 2; rr++) {
            int d = 2*gg + rr;
            const char* src = PbC + (size_t)(rowbase + d)*1024 + lane*32;
            uint32_t dst = ringbase + d*1024 + lane*32;
            cp16(dst, src);
            cp16(dst + 16, src + 16);
        }
        asm volatile("cp.async.commit_group;");
    }
    #pragma unroll 4
    for (int g = 0; g < 16; g++) {
        if (g < 14)       asm volatile("cp.async.wait_group 2;");
        else if (g == 14) asm volatile("cp.async.wait_group 1;");
        else              asm volatile("cp.async.wait_group 0;");
        __syncwarp();
        int r0 = 2*g, r1 = 2*g + 1;
        const uint4* sl0 = ringw + (size_t)(r0 & 7)*64;
        const uint4* sl1 = ringw + (size_t)(r1 & 7)*64;
        uint4 qa = sl0[lane], qb = sl0[lane + 32];
        uint4 qc = sl1[lane], qd = sl1[lane + 32];
        float p0[16], p1[16];
        unpack8(qa, p0); unpack8(qb, p0+8);
        unpack8(qc, p1); unpack8(qd, p1+8);
        __syncwarp();
        if (g + 3 < 16) {
            #pragma unroll
            for (int rr = 0; rr < 2; rr++) {
                int d = 2*(g+3) + rr;
                const char* src = PbC + (size_t)(rowbase + d)*1024 + lane*32;
                uint32_t dst = ringbase + (d & 7)*1024 + lane*32;
                cp16(dst, src);
                cp16(dst + 16, src + 16);
            }
            asm volatile("cp.async.commit_group;");
        }
        float k0a = 0.f, k0b = 0.f, k1a = 0.f, k1b = 0.f;
        #pragma unroll
        for (int i = 0; i < 8; i++) {
            k0a = fmaf(p0[i],   ur[i],   k0a);
            k0b = fmaf(p0[8+i], ur[8+i], k0b);
            k1a = fmaf(p1[i],   ur[i],   k1a);
            k1b = fmaf(p1[8+i], ur[8+i], k1b);
        }
        float ks0 = k0a + k0b, ks1 = k1a + k1b;
        #pragma unroll
        for (int o = 16; o > 0; o >>= 1) {
            ks0 += __shfl_xor_sync(0xFFFFFFFFu, ks0, o);
            ks1 += __shfl_xor_sync(0xFFFFFFFFu, ks1, o);
        }
        float iR0 = s_irs[w*32 + r0], iR1 = s_irs[w*32 + r1];
        float er0 = fmaxf(0.f, 1.f - iR0*ks0);
        float er1 = fmaxf(0.f, 1.f - iR1*ks1);
        float l10 = s_lp1h[w*32 + r0], l11 = s_lp1h[w*32 + r1];
        float v0[16], v1[16];
        #pragma unroll
        for (int i = 0; i < 16; i++) {
            v0[i] = l10 + __logf(fmaf(p0[i], ur[i]*iR0, er0*er[i]));
            v1[i] = l11 + __logf(fmaf(p1[i], ur[i]*iR1, er1*er[i]));
        }
        float* o00 = Ob + (size_t)(rowbase + r0)*512 + 8*lane;
        float* o10 = Ob + (size_t)(rowbase + r1)*512 + 8*lane;
        *(float4*)(o00      ) = make_float4(v0[0], v0[1], v0[2], v0[3]);
        *(float4*)(o00 + 4  ) = make_float4(v0[4], v0[5], v0[6], v0[7]);
        *(float4*)(o00 + 256) = make_float4(v0[8], v0[9], v0[10], v0[11]);
        *(float4*)(o00 + 260) = make_float4(v0[12], v0[13], v0[14], v0[15]);
        *(float4*)(o10      ) = make_float4(v1[0], v1[1], v1[2], v1[3]);
        *(float4*)(o10 + 4  ) = make_float4(v1[4], v1[5], v1[6], v1[7]);
        *(float4*)(o10 + 256) = make_float4(v1[8], v1[9], v1[10], v1[11]);
        *(float4*)(o10 + 260) = make_float4(v1[12], v1[13], v1[14], v1[15]);
    }
}

// ---------------- launch ----------------
extern "C" void kernel_launch(void* const* d_in, const int* in_sizes, int n_in,
                              void* d_out, int out_size) {
    const float* s_logits = (const float*)d_in[0];
    const float* W1   = (const float*)d_in[1];
    const float* b1   = (const float*)d_in[2];
    const float* W2   = (const float*)d_in[3];
    const float* b2   = (const float*)d_in[4];
    const float* Wout = (const float*)d_in[5];
    const float* bout = (const float*)d_in[6];
    const float* prior= (const float*)d_in[7];
    float* out = (float*)d_out;
    (void)in_sizes; (void)n_in; (void)out_size;

    cudaFuncSetAttribute(k_gemm, cudaFuncAttributeMaxDynamicSharedMemorySize, SMEM_TOTAL_GEMM);
    cudaFuncSetAttribute(k_sinkp2, cudaFuncAttributeMaxDynamicSharedMemorySize, SMEM_TOTAL_SINK);

    k_prior<<<1, 1024>>>(prior);
    k_mlp<<<Bb, 512>>>(s_logits, W1, b1, W2, b2);
    k_gemm<<<2048, 256, SMEM_TOTAL_GEMM>>>(Wout, bout);
    k_sinkp2<<<2*Bb, 512, SMEM_TOTAL_SINK>>>(out);
}